// round 3
// baseline (speedup 1.0000x reference)
#include <cuda_runtime.h>
#include <cuda_bf16.h>
#include <cstdint>
#include <cstddef>

// Problem dims
#define B_ 4
#define M_ 256
#define N_ 128
#define D_ 512
#define C_ 1024
#define R_TOTAL (B_*M_*N_)    // 131072 rows of the big GEMM
#define RB 128                // rows per row-block
#define NUM_RB (R_TOTAL/RB)   // 1024

// ---------------- scratch (device globals; no runtime alloc) ----------------
__device__ float g_he[B_*M_*D_];                           // 2 MB
__device__ float g_hd[B_*N_*D_];                           // 1 MB
__device__ __nv_bfloat16 g_w2b[C_*D_];                     // 1 MB
__device__ __nv_bfloat16 g_hid[(size_t)R_TOTAL * D_];      // 128 MB
__device__ __nv_bfloat16 g_logits[(size_t)R_TOTAL * C_];   // 268 MB
__device__ float g_part[(size_t)R_TOTAL * 16];             // 8 MB  [row][8 groups][max,sum]

// ---------------- helpers ----------------
__device__ __forceinline__ uint32_t smem_u32(const void* p) {
    uint32_t a;
    asm("{ .reg .u64 t; cvta.to.shared.u64 t, %1; cvt.u32.u64 %0, t; }" : "=r"(a) : "l"(p));
    return a;
}
#define SW128(o) ((o) ^ (((o) >> 3) & 0x70))

__device__ __forceinline__ void cp16(uint32_t s, const void* g) {
    asm volatile("cp.async.cg.shared.global [%0], [%1], 16;" :: "r"(s), "l"(g));
}
#define CP_COMMIT() asm volatile("cp.async.commit_group;" ::: "memory")
#define CP_WAIT(n)  asm volatile("cp.async.wait_group %0;" :: "n"(n) : "memory")

__device__ __forceinline__ void ldsm_x4(uint32_t* r, uint32_t addr) {
    asm volatile("ldmatrix.sync.aligned.m8n8.x4.shared.b16 {%0,%1,%2,%3}, [%4];"
                 : "=r"(r[0]), "=r"(r[1]), "=r"(r[2]), "=r"(r[3]) : "r"(addr));
}
__device__ __forceinline__ void mma16816(float* c, const uint32_t* a, const uint32_t* b) {
    asm volatile(
        "mma.sync.aligned.m16n8k16.row.col.f32.bf16.bf16.f32 "
        "{%0,%1,%2,%3}, {%4,%5,%6,%7}, {%8,%9}, {%0,%1,%2,%3};"
        : "+f"(c[0]), "+f"(c[1]), "+f"(c[2]), "+f"(c[3])
        : "r"(a[0]), "r"(a[1]), "r"(a[2]), "r"(a[3]), "r"(b[0]), "r"(b[1]));
}

// ---------------- K0: w2 fp32 -> bf16 ----------------
__global__ void __launch_bounds__(256) k_w2conv(const float* __restrict__ w2) {
    int idx = (blockIdx.x * 256 + threadIdx.x) * 4;
    if (idx < C_ * D_) {
        float4 v = *(const float4*)(w2 + idx);
        __nv_bfloat16 o[4];
        o[0] = __float2bfloat16(v.x); o[1] = __float2bfloat16(v.y);
        o[2] = __float2bfloat16(v.z); o[3] = __float2bfloat16(v.w);
        *(uint2*)(g_w2b + idx) = *(uint2*)o;
    }
}

// ---------------- K1: he/hd = enc/dec @ w1 slices (fp32) ----------------
__global__ void __launch_bounds__(256) k_fc1(const float* __restrict__ enc,
                                             const float* __restrict__ dec,
                                             const float* __restrict__ w1) {
    __shared__ float rows_s[16][D_];
    int row0 = blockIdx.x * 16;
    const float* src; float* dst; int woff;
    if (row0 < B_ * M_) { src = enc + (size_t)row0 * D_; dst = g_he + (size_t)row0 * D_; woff = 0; }
    else {
        int r2 = row0 - B_ * M_;
        src = dec + (size_t)r2 * D_; dst = g_hd + (size_t)r2 * D_; woff = D_;
    }
    for (int i = threadIdx.x; i < 16 * D_ / 4; i += 256) {
        float4 v = ((const float4*)src)[i];
        int r = i >> 7, c4 = i & 127;
        *(float4*)&rows_s[r][c4 * 4] = v;
    }
    __syncthreads();
    int wid = threadIdx.x >> 5, lid = threadIdx.x & 31;
    for (int e = wid * 64; e < wid * 64 + 64; e++) {
        const float4* wr = (const float4*)(w1 + (size_t)e * (2 * D_) + woff);
        float4 wv[4];
        #pragma unroll
        for (int q = 0; q < 4; q++) wv[q] = wr[lid + q * 32];
        #pragma unroll
        for (int r = 0; r < 16; r++) {
            float acc = 0.f;
            #pragma unroll
            for (int q = 0; q < 4; q++) {
                float4 ev = *(const float4*)&rows_s[r][(lid + q * 32) * 4];
                acc += wv[q].x * ev.x + wv[q].y * ev.y + wv[q].z * ev.z + wv[q].w * ev.w;
            }
            #pragma unroll
            for (int o = 16; o; o >>= 1) acc += __shfl_xor_sync(0xFFFFFFFFu, acc, o);
            if (lid == 0) dst[(size_t)r * D_ + e] = acc;
        }
    }
}

// ---------------- K2: hid = bf16(tanh(he + hd + b1)) ----------------
__global__ void __launch_bounds__(256) k_hid(const float* __restrict__ b1) {
    __shared__ float he_s[D_], b1_s[D_];
    int bm = blockIdx.x;             // b*256+m
    int b = bm >> 8;
    for (int i = threadIdx.x; i < D_; i += 256) {
        he_s[i] = g_he[(size_t)bm * D_ + i];
        b1_s[i] = b1[i];
    }
    __syncthreads();
    const float* hdb = g_hd + (size_t)b * N_ * D_;
    __nv_bfloat16* outp = g_hid + (size_t)bm * N_ * D_;
    for (int idx = threadIdx.x; idx < N_ * D_ / 8; idx += 256) {
        int n = idx >> 6, k = (idx & 63) * 8;
        float4 a0 = *(const float4*)(hdb + (size_t)n * D_ + k);
        float4 a1 = *(const float4*)(hdb + (size_t)n * D_ + k + 4);
        float v[8] = {a0.x, a0.y, a0.z, a0.w, a1.x, a1.y, a1.z, a1.w};
        __nv_bfloat16 o[8];
        #pragma unroll
        for (int j = 0; j < 8; j++) {
            float x = v[j] + he_s[k + j] + b1_s[k + j];
            float t; asm("tanh.approx.f32 %0, %1;" : "=f"(t) : "f"(x));
            o[j] = __float2bfloat16(t);
        }
        *(uint4*)(outp + (size_t)n * D_ + k) = *(uint4*)o;
    }
}

// ---------------- G1: bf16 mma.sync GEMM + b2 + partial softmax + bf16 logits ----------------
// smem layout (dynamic):
#define SA   0          // A tiles: 2 x 16384 (128 rows x 128B, SW128)
#define SB   32768      // B tiles: 2 x 16384
#define SB2  65536      // 128 floats (b2 slice)
#define SPM  66048      // 128 x 2 floats (per-row max per wn)
#define SPS  67072      // 128 x 2 floats (per-row sum per wn)
#define STG  0          // stage (reuses A/B): 128 x 136 bf16 = 34816 B
#define SMEM_G1 68096
#define STG_STRIDE 272  // bytes per stage row (136 bf16)

__global__ void __launch_bounds__(256, 2)
k_gemm(const float* __restrict__ b2) {
    extern __shared__ char sm[];
    uint32_t sb = smem_u32(sm);
    int tid = threadIdx.x, wid = tid >> 5, lane = tid & 31;
    int rb = blockIdx.x >> 3, cg = blockIdx.x & 7;
    int m0 = (wid >> 1) * 32, n0 = (wid & 1) * 64;
    int g = lane >> 2, t4 = lane & 3;

    if (tid < 128) ((float*)(sm + SB2))[tid] = b2[cg * 128 + tid];

    const __nv_bfloat16* Ag = g_hid + (size_t)rb * RB * D_;
    const __nv_bfloat16* Bg = g_w2b + (size_t)cg * 128 * D_;

    float c[2][8][4];
    #pragma unroll
    for (int i = 0; i < 2; i++)
        #pragma unroll
        for (int j = 0; j < 8; j++)
            #pragma unroll
            for (int q = 0; q < 4; q++) c[i][j][q] = 0.f;

    // ---- load tile for K-chunk kc into buffer buf ----
    auto load_tiles = [&](int kc, int buf) {
        uint32_t sa = sb + SA + buf * 16384;
        uint32_t sB = sb + SB + buf * 16384;
        #pragma unroll
        for (int i = 0; i < 4; i++) {
            int idx = tid + i * 256;          // 1024 chunks of 16B
            int row = idx >> 3, ck = idx & 7;
            const __nv_bfloat16* ga = Ag + (size_t)row * D_ + kc * 64 + ck * 8;
            const __nv_bfloat16* gb = Bg + (size_t)row * D_ + kc * 64 + ck * 8;
            uint32_t so = SW128(row * 128 + ck * 16);
            cp16(sa + so, ga);
            cp16(sB + so, gb);
        }
    };

    load_tiles(0, 0);
    CP_COMMIT();

    for (int kc = 0; kc < 8; kc++) {
        int buf = kc & 1;
        if (kc < 7) {
            load_tiles(kc + 1, buf ^ 1);
            CP_COMMIT();
            CP_WAIT(1);
        } else {
            CP_WAIT(0);
        }
        __syncthreads();
        uint32_t sa = sb + SA + buf * 16384;
        uint32_t sB = sb + SB + buf * 16384;
        #pragma unroll
        for (int ks = 0; ks < 4; ks++) {
            int k0 = ks * 16;
            uint32_t a[2][4];
            #pragma unroll
            for (int mt = 0; mt < 2; mt++) {
                int row = m0 + mt * 16 + (lane & 15);
                int cb = (k0 + ((lane >> 4) << 3)) * 2;
                ldsm_x4(a[mt], sa + SW128(row * 128 + cb));
            }
            uint32_t b[8][2];
            #pragma unroll
            for (int ntp = 0; ntp < 4; ntp++) {
                int row = n0 + ntp * 16 + ((lane & 16) >> 1) + (lane & 7);
                int cb = (k0 + (lane & 8)) * 2;
                uint32_t r[4];
                ldsm_x4(r, sB + SW128(row * 128 + cb));
                b[ntp * 2][0] = r[0]; b[ntp * 2][1] = r[1];
                b[ntp * 2 + 1][0] = r[2]; b[ntp * 2 + 1][1] = r[3];
            }
            #pragma unroll
            for (int mt = 0; mt < 2; mt++)
                #pragma unroll
                for (int nt = 0; nt < 8; nt++)
                    mma16816(c[mt][nt], a[mt], b[nt]);
        }
        __syncthreads();
    }

    // ---------------- epilogue ----------------
    const float* b2s = (const float*)(sm + SB2);
    float* pmS = (float*)(sm + SPM);
    float* psS = (float*)(sm + SPS);
    const float NEG_INF = __int_as_float(0xff800000);

    // add b2; per-row (max, sumexp); write bf16 pairs to stage
    #pragma unroll
    for (int mt = 0; mt < 2; mt++) {
        #pragma unroll
        for (int half = 0; half < 2; half++) {
            int rl = m0 + mt * 16 + half * 8 + g;
            float mx = NEG_INF;
            #pragma unroll
            for (int nt = 0; nt < 8; nt++) {
                int col = n0 + nt * 8 + t4 * 2;
                float v0 = c[mt][nt][half * 2]     + b2s[col];
                float v1 = c[mt][nt][half * 2 + 1] + b2s[col + 1];
                c[mt][nt][half * 2] = v0;
                c[mt][nt][half * 2 + 1] = v1;
                mx = fmaxf(mx, fmaxf(v0, v1));
            }
            float sum = 0.f;
            #pragma unroll
            for (int nt = 0; nt < 8; nt++) {
                sum += __expf(c[mt][nt][half * 2]     - mx);
                sum += __expf(c[mt][nt][half * 2 + 1] - mx);
            }
            #pragma unroll
            for (int off = 1; off <= 2; off <<= 1) {
                float om = __shfl_xor_sync(0xFFFFFFFFu, mx, off);
                float os = __shfl_xor_sync(0xFFFFFFFFu, sum, off);
                float nm = fmaxf(mx, om);
                sum = sum * __expf(mx - nm) + os * __expf(om - nm);
                mx = nm;
            }
            if (t4 == 0) {
                pmS[rl * 2 + (wid & 1)] = mx;
                psS[rl * 2 + (wid & 1)] = sum;
            }
            // stage bf16 pairs
            #pragma unroll
            for (int nt = 0; nt < 8; nt++) {
                int col = n0 + nt * 8 + t4 * 2;
                __nv_bfloat162 p;
                p.x = __float2bfloat16(c[mt][nt][half * 2]);
                p.y = __float2bfloat16(c[mt][nt][half * 2 + 1]);
                *(uint32_t*)(sm + STG + rl * STG_STRIDE + col * 2) = *(uint32_t*)&p;
            }
        }
    }
    __syncthreads();

    if (tid < 128) {
        float ma = pmS[tid * 2], mb = pmS[tid * 2 + 1];
        float sa = psS[tid * 2], sbv = psS[tid * 2 + 1];
        float Mx = fmaxf(ma, mb);
        float S = sa * __expf(ma - Mx) + sbv * __expf(mb - Mx);
        size_t rowg = (size_t)rb * RB + tid;
        float2 pr; pr.x = Mx; pr.y = S;
        *(float2*)(g_part + rowg * 16 + cg * 2) = pr;
    }

    // copy staged bf16 logits to gmem (coalesced)
    #pragma unroll
    for (int i = 0; i < 8; i++) {
        int idx = tid + i * 256;          // 2048 chunks of 16B
        int row = idx >> 4, ck = idx & 15;
        uint4 v = *(uint4*)(sm + STG + row * STG_STRIDE + ck * 16);
        *(uint4*)(g_logits + ((size_t)rb * RB + row) * C_ + cg * 128 + ck * 8) = v;
    }
}

// ---------------- G2: lse combine + final write ----------------
__global__ void __launch_bounds__(256) k_out(float* __restrict__ out) {
    int tid = threadIdx.x;
    size_t row = (size_t)blockIdx.x * 2 + (tid >> 7);
    int col = (tid & 127) * 8;

    const float2* pp = (const float2*)(g_part + row * 16);
    float2 p[8];
    float Mx = __int_as_float(0xff800000);
    #pragma unroll
    for (int i = 0; i < 8; i++) { p[i] = pp[i]; Mx = fmaxf(Mx, p[i].x); }
    float S = 0.f;
    #pragma unroll
    for (int i = 0; i < 8; i++) S += p[i].y * __expf(p[i].x - Mx);
    float lse = Mx + __logf(S);

    uint4 lv = *(const uint4*)(g_logits + row * C_ + col);
    __nv_bfloat16* lb = (__nv_bfloat16*)&lv;
    float4 o0, o1;
    o0.x = __bfloat162float(lb[0]) - lse;
    o0.y = __bfloat162float(lb[1]) - lse;
    o0.z = __bfloat162float(lb[2]) - lse;
    o0.w = __bfloat162float(lb[3]) - lse;
    o1.x = __bfloat162float(lb[4]) - lse;
    o1.y = __bfloat162float(lb[5]) - lse;
    o1.z = __bfloat162float(lb[6]) - lse;
    o1.w = __bfloat162float(lb[7]) - lse;
    *(float4*)(out + row * C_ + col) = o0;
    *(float4*)(out + row * C_ + col + 4) = o1;
}

// ---------------- launch ----------------
extern "C" void kernel_launch(void* const* d_in, const int* in_sizes, int n_in,
                              void* d_out, int out_size) {
    const float* enc = (const float*)d_in[0];
    const float* dec = (const float*)d_in[1];
    const float* w1  = (const float*)d_in[2];
    const float* b1  = (const float*)d_in[3];
    const float* w2  = (const float*)d_in[4];
    const float* b2  = (const float*)d_in[5];
    float* out = (float*)d_out;

    k_w2conv<<<(C_ * D_ / 4 + 255) / 256, 256>>>(w2);
    k_fc1<<<(B_ * M_ + B_ * N_) / 16, 256>>>(enc, dec, w1);
    k_hid<<<B_ * M_, 256>>>(b1);
    static int smem_set = 0;
    if (!smem_set) {
        cudaFuncSetAttribute(k_gemm, cudaFuncAttributeMaxDynamicSharedMemorySize, SMEM_G1);
        smem_set = 1;
    }
    k_gemm<<<NUM_RB * 8, 256, SMEM_G1>>>(b2);
    k_out<<<R_TOTAL / 2, 256>>>(out);
}

// round 4
// speedup vs baseline: 1.0234x; 1.0234x over previous
#include <cuda_runtime.h>
#include <cuda_bf16.h>
#include <cstdint>
#include <cstddef>

// Problem dims
#define B_ 4
#define M_ 256
#define N_ 128
#define D_ 512
#define C_ 1024
#define R_TOTAL (B_*M_*N_)    // 131072 rows of the big GEMM
#define RB 128                // rows per row-block
#define NUM_RB (R_TOTAL/RB)   // 1024

// ---------------- scratch (device globals; no runtime alloc) ----------------
__device__ float g_he[B_*M_*D_];                           // 2 MB
__device__ float g_hd[B_*N_*D_];                           // 1 MB
__device__ __nv_bfloat16 g_w2b[C_*D_];                     // 1 MB
__device__ __nv_bfloat16 g_hid[(size_t)R_TOTAL * D_];      // 128 MB
__device__ __nv_bfloat16 g_logits[(size_t)R_TOTAL * C_];   // 268 MB

// ---------------- helpers ----------------
__device__ __forceinline__ uint32_t smem_u32(const void* p) {
    uint32_t a;
    asm("{ .reg .u64 t; cvta.to.shared.u64 t, %1; cvt.u32.u64 %0, t; }" : "=r"(a) : "l"(p));
    return a;
}
#define SW128(o) ((o) ^ (((o) >> 3) & 0x70))

__device__ __forceinline__ void cp16(uint32_t s, const void* g) {
    asm volatile("cp.async.cg.shared.global [%0], [%1], 16;" :: "r"(s), "l"(g));
}
#define CP_COMMIT() asm volatile("cp.async.commit_group;" ::: "memory")
#define CP_WAIT(n)  asm volatile("cp.async.wait_group %0;" :: "n"(n) : "memory")

__device__ __forceinline__ void ldsm_x4(uint32_t* r, uint32_t addr) {
    asm volatile("ldmatrix.sync.aligned.m8n8.x4.shared.b16 {%0,%1,%2,%3}, [%4];"
                 : "=r"(r[0]), "=r"(r[1]), "=r"(r[2]), "=r"(r[3]) : "r"(addr));
}
__device__ __forceinline__ void mma16816(float* c, const uint32_t* a, const uint32_t* b) {
    asm volatile(
        "mma.sync.aligned.m16n8k16.row.col.f32.bf16.bf16.f32 "
        "{%0,%1,%2,%3}, {%4,%5,%6,%7}, {%8,%9}, {%0,%1,%2,%3};"
        : "+f"(c[0]), "+f"(c[1]), "+f"(c[2]), "+f"(c[3])
        : "r"(a[0]), "r"(a[1]), "r"(a[2]), "r"(a[3]), "r"(b[0]), "r"(b[1]));
}

// ---------------- K0: w2 fp32 -> bf16 ----------------
__global__ void __launch_bounds__(256) k_w2conv(const float* __restrict__ w2) {
    int idx = (blockIdx.x * 256 + threadIdx.x) * 4;
    if (idx < C_ * D_) {
        float4 v = *(const float4*)(w2 + idx);
        __nv_bfloat16 o[4];
        o[0] = __float2bfloat16(v.x); o[1] = __float2bfloat16(v.y);
        o[2] = __float2bfloat16(v.z); o[3] = __float2bfloat16(v.w);
        *(uint2*)(g_w2b + idx) = *(uint2*)o;
    }
}

// ---------------- K1: he/hd = enc/dec @ w1 slices (fp32) ----------------
__global__ void __launch_bounds__(256) k_fc1(const float* __restrict__ enc,
                                             const float* __restrict__ dec,
                                             const float* __restrict__ w1) {
    __shared__ float rows_s[16][D_];
    int row0 = blockIdx.x * 16;
    const float* src; float* dst; int woff;
    if (row0 < B_ * M_) { src = enc + (size_t)row0 * D_; dst = g_he + (size_t)row0 * D_; woff = 0; }
    else {
        int r2 = row0 - B_ * M_;
        src = dec + (size_t)r2 * D_; dst = g_hd + (size_t)r2 * D_; woff = D_;
    }
    for (int i = threadIdx.x; i < 16 * D_ / 4; i += 256) {
        float4 v = ((const float4*)src)[i];
        int r = i >> 7, c4 = i & 127;
        *(float4*)&rows_s[r][c4 * 4] = v;
    }
    __syncthreads();
    int wid = threadIdx.x >> 5, lid = threadIdx.x & 31;
    for (int e = wid * 64; e < wid * 64 + 64; e++) {
        const float4* wr = (const float4*)(w1 + (size_t)e * (2 * D_) + woff);
        float4 wv[4];
        #pragma unroll
        for (int q = 0; q < 4; q++) wv[q] = wr[lid + q * 32];
        #pragma unroll
        for (int r = 0; r < 16; r++) {
            float acc = 0.f;
            #pragma unroll
            for (int q = 0; q < 4; q++) {
                float4 ev = *(const float4*)&rows_s[r][(lid + q * 32) * 4];
                acc += wv[q].x * ev.x + wv[q].y * ev.y + wv[q].z * ev.z + wv[q].w * ev.w;
            }
            #pragma unroll
            for (int o = 16; o; o >>= 1) acc += __shfl_xor_sync(0xFFFFFFFFu, acc, o);
            if (lid == 0) dst[(size_t)r * D_ + e] = acc;
        }
    }
}

// ---------------- K2: hid = bf16(tanh(he + hd + b1)) ----------------
__global__ void __launch_bounds__(256) k_hid(const float* __restrict__ b1) {
    __shared__ float he_s[D_], b1_s[D_];
    int bm = blockIdx.x;             // b*256+m
    int b = bm >> 8;
    for (int i = threadIdx.x; i < D_; i += 256) {
        he_s[i] = g_he[(size_t)bm * D_ + i];
        b1_s[i] = b1[i];
    }
    __syncthreads();
    const float* hdb = g_hd + (size_t)b * N_ * D_;
    __nv_bfloat16* outp = g_hid + (size_t)bm * N_ * D_;
    for (int idx = threadIdx.x; idx < N_ * D_ / 8; idx += 256) {
        int n = idx >> 6, k = (idx & 63) * 8;
        float4 a0 = *(const float4*)(hdb + (size_t)n * D_ + k);
        float4 a1 = *(const float4*)(hdb + (size_t)n * D_ + k + 4);
        float v[8] = {a0.x, a0.y, a0.z, a0.w, a1.x, a1.y, a1.z, a1.w};
        __nv_bfloat16 o[8];
        #pragma unroll
        for (int j = 0; j < 8; j++) {
            float x = v[j] + he_s[k + j] + b1_s[k + j];
            float t; asm("tanh.approx.f32 %0, %1;" : "=f"(t) : "f"(x));
            o[j] = __float2bfloat16(t);
        }
        *(uint4*)(outp + (size_t)n * D_ + k) = *(uint4*)o;
    }
}

// ---------------- G1: fused GEMM (all 8 col-groups per CTA) + log-softmax + output ----------------
// smem layout (dynamic):
#define SA    0          // A tiles: 2 x 16384 (128 rows x 128B, SW128)
#define SB    32768      // B tiles: 2 x 16384
#define SB2   65536      // 1024 floats (full b2)
#define SPM   69632      // 128 x 2 floats
#define SPS   70656      // 128 x 2 floats
#define SPART 71680      // 128 rows x 8 cg x 2 floats = 8192 B
#define SLSE  79872      // 128 floats
#define STG   0          // stage (reuses A + start of B): 128 x 136 bf16 = 34816 B
#define SMEM_G1 80384
#define STG_STRIDE 272   // bytes per stage row (136 bf16)

__global__ void __launch_bounds__(256, 2)
k_gemm(float* __restrict__ out, const float* __restrict__ b2) {
    extern __shared__ char sm[];
    uint32_t sb = smem_u32(sm);
    int tid = threadIdx.x, wid = tid >> 5, lane = tid & 31;
    int rb = blockIdx.x;
    int m0 = (wid >> 1) * 32, n0 = (wid & 1) * 64;
    int g = lane >> 2, t4 = lane & 3;
    const float NEG_INF = __int_as_float(0xff800000);

    for (int i = tid; i < C_; i += 256) ((float*)(sm + SB2))[i] = b2[i];

    const __nv_bfloat16* Ag = g_hid + (size_t)rb * RB * D_;
    float* pmS = (float*)(sm + SPM);
    float* psS = (float*)(sm + SPS);
    float* part = (float*)(sm + SPART);
    __syncthreads();

    for (int cg = 0; cg < 8; cg++) {
        const __nv_bfloat16* Bg = g_w2b + (size_t)cg * 128 * D_;
        const float* b2s = (const float*)(sm + SB2) + cg * 128;

        float c[2][8][4];
        #pragma unroll
        for (int i = 0; i < 2; i++)
            #pragma unroll
            for (int j = 0; j < 8; j++)
                #pragma unroll
                for (int q = 0; q < 4; q++) c[i][j][q] = 0.f;

        auto load_tiles = [&](int kc, int buf) {
            uint32_t sa = sb + SA + buf * 16384;
            uint32_t sB = sb + SB + buf * 16384;
            #pragma unroll
            for (int i = 0; i < 4; i++) {
                int idx = tid + i * 256;          // 1024 chunks of 16B
                int row = idx >> 3, ck = idx & 7;
                const __nv_bfloat16* ga = Ag + (size_t)row * D_ + kc * 64 + ck * 8;
                const __nv_bfloat16* gb = Bg + (size_t)row * D_ + kc * 64 + ck * 8;
                uint32_t so = SW128(row * 128 + ck * 16);
                cp16(sa + so, ga);
                cp16(sB + so, gb);
            }
        };

        load_tiles(0, 0);
        CP_COMMIT();

        for (int kc = 0; kc < 8; kc++) {
            int buf = kc & 1;
            if (kc < 7) {
                load_tiles(kc + 1, buf ^ 1);
                CP_COMMIT();
                CP_WAIT(1);
            } else {
                CP_WAIT(0);
            }
            __syncthreads();
            uint32_t sa = sb + SA + buf * 16384;
            uint32_t sB = sb + SB + buf * 16384;
            #pragma unroll
            for (int ks = 0; ks < 4; ks++) {
                int k0 = ks * 16;
                uint32_t a[2][4];
                #pragma unroll
                for (int mt = 0; mt < 2; mt++) {
                    int row = m0 + mt * 16 + (lane & 15);
                    int cb = (k0 + ((lane >> 4) << 3)) * 2;
                    ldsm_x4(a[mt], sa + SW128(row * 128 + cb));
                }
                uint32_t b[8][2];
                #pragma unroll
                for (int ntp = 0; ntp < 4; ntp++) {
                    int row = n0 + ntp * 16 + ((lane & 16) >> 1) + (lane & 7);
                    int cb = (k0 + (lane & 8)) * 2;
                    uint32_t r[4];
                    ldsm_x4(r, sB + SW128(row * 128 + cb));
                    b[ntp * 2][0] = r[0]; b[ntp * 2][1] = r[1];
                    b[ntp * 2 + 1][0] = r[2]; b[ntp * 2 + 1][1] = r[3];
                }
                #pragma unroll
                for (int mt = 0; mt < 2; mt++)
                    #pragma unroll
                    for (int nt = 0; nt < 8; nt++)
                        mma16816(c[mt][nt], a[mt], b[nt]);
            }
            __syncthreads();
        }

        // ---- per-cg epilogue: b2, (max,sum), stage bf16 ----
        #pragma unroll
        for (int mt = 0; mt < 2; mt++) {
            #pragma unroll
            for (int half = 0; half < 2; half++) {
                int rl = m0 + mt * 16 + half * 8 + g;
                float mx = NEG_INF;
                #pragma unroll
                for (int nt = 0; nt < 8; nt++) {
                    int col = n0 + nt * 8 + t4 * 2;
                    float v0 = c[mt][nt][half * 2]     + b2s[col];
                    float v1 = c[mt][nt][half * 2 + 1] + b2s[col + 1];
                    c[mt][nt][half * 2] = v0;
                    c[mt][nt][half * 2 + 1] = v1;
                    mx = fmaxf(mx, fmaxf(v0, v1));
                }
                float sum = 0.f;
                #pragma unroll
                for (int nt = 0; nt < 8; nt++) {
                    sum += __expf(c[mt][nt][half * 2]     - mx);
                    sum += __expf(c[mt][nt][half * 2 + 1] - mx);
                }
                #pragma unroll
                for (int off = 1; off <= 2; off <<= 1) {
                    float om = __shfl_xor_sync(0xFFFFFFFFu, mx, off);
                    float os = __shfl_xor_sync(0xFFFFFFFFu, sum, off);
                    float nm = fmaxf(mx, om);
                    sum = sum * __expf(mx - nm) + os * __expf(om - nm);
                    mx = nm;
                }
                if (t4 == 0) {
                    pmS[rl * 2 + (wid & 1)] = mx;
                    psS[rl * 2 + (wid & 1)] = sum;
                }
                #pragma unroll
                for (int nt = 0; nt < 8; nt++) {
                    int col = n0 + nt * 8 + t4 * 2;
                    __nv_bfloat162 p;
                    p.x = __float2bfloat16(c[mt][nt][half * 2]);
                    p.y = __float2bfloat16(c[mt][nt][half * 2 + 1]);
                    *(uint32_t*)(sm + STG + rl * STG_STRIDE + col * 2) = *(uint32_t*)&p;
                }
            }
        }
        __syncthreads();

        if (tid < 128) {
            float ma = pmS[tid * 2], mb = pmS[tid * 2 + 1];
            float sa2 = psS[tid * 2], sbv = psS[tid * 2 + 1];
            float Mx = fmaxf(ma, mb);
            float S = sa2 * __expf(ma - Mx) + sbv * __expf(mb - Mx);
            part[tid * 16 + cg * 2]     = Mx;
            part[tid * 16 + cg * 2 + 1] = S;
        }

        // staged bf16 logits -> gmem (coalesced)
        #pragma unroll
        for (int i = 0; i < 8; i++) {
            int idx = tid + i * 256;          // 2048 chunks of 16B
            int row = idx >> 4, ck = idx & 15;
            uint4 v = *(uint4*)(sm + STG + row * STG_STRIDE + ck * 16);
            *(uint4*)(g_logits + ((size_t)rb * RB + row) * C_ + cg * 128 + ck * 8) = v;
        }
        __syncthreads();   // protect SA/SB (stage region) before next cg's loads
    }

    // ---- lse per row ----
    if (tid < 128) {
        float Mx = NEG_INF;
        #pragma unroll
        for (int i = 0; i < 8; i++) Mx = fmaxf(Mx, part[tid * 16 + i * 2]);
        float S = 0.f;
        #pragma unroll
        for (int i = 0; i < 8; i++)
            S += part[tid * 16 + i * 2 + 1] * __expf(part[tid * 16 + i * 2] - Mx);
        ((float*)(sm + SLSE))[tid] = Mx + __logf(S);
    }
    __syncthreads();

    // ---- pass 2: re-read own logits (hot in L2), subtract lse, write fp32 out ----
    const float* lseS = (const float*)(sm + SLSE);
    #pragma unroll
    for (int i = 0; i < 64; i++) {
        int idx = tid + i * 256;              // 16384 chunks of 16B over 128x1024
        int row = idx >> 7, ck = idx & 127;
        float lse = lseS[row];
        uint4 lv = *(const uint4*)(g_logits + ((size_t)rb * RB + row) * C_ + ck * 8);
        __nv_bfloat16* lb = (__nv_bfloat16*)&lv;
        float4 o0, o1;
        o0.x = __bfloat162float(lb[0]) - lse;
        o0.y = __bfloat162float(lb[1]) - lse;
        o0.z = __bfloat162float(lb[2]) - lse;
        o0.w = __bfloat162float(lb[3]) - lse;
        o1.x = __bfloat162float(lb[4]) - lse;
        o1.y = __bfloat162float(lb[5]) - lse;
        o1.z = __bfloat162float(lb[6]) - lse;
        o1.w = __bfloat162float(lb[7]) - lse;
        float* op = out + ((size_t)rb * RB + row) * C_ + ck * 8;
        *(float4*)op = o0;
        *(float4*)(op + 4) = o1;
    }
}

// ---------------- launch ----------------
extern "C" void kernel_launch(void* const* d_in, const int* in_sizes, int n_in,
                              void* d_out, int out_size) {
    const float* enc = (const float*)d_in[0];
    const float* dec = (const float*)d_in[1];
    const float* w1  = (const float*)d_in[2];
    const float* b1  = (const float*)d_in[3];
    const float* w2  = (const float*)d_in[4];
    const float* b2  = (const float*)d_in[5];
    float* out = (float*)d_out;

    k_w2conv<<<(C_ * D_ / 4 + 255) / 256, 256>>>(w2);
    k_fc1<<<(B_ * M_ + B_ * N_) / 16, 256>>>(enc, dec, w1);
    k_hid<<<B_ * M_, 256>>>(b1);
    static int smem_set = 0;
    if (!smem_set) {
        cudaFuncSetAttribute(k_gemm, cudaFuncAttributeMaxDynamicSharedMemorySize, SMEM_G1);
        smem_set = 1;
    }
    k_gemm<<<NUM_RB, 256, SMEM_G1>>>(out, b2);
}

// round 5
// speedup vs baseline: 1.1209x; 1.0952x over previous
#include <cuda_runtime.h>
#include <cuda_bf16.h>
#include <cstdint>
#include <cstddef>

// Problem dims
#define B_ 4
#define M_ 256
#define N_ 128
#define D_ 512
#define C_ 1024
#define R_TOTAL (B_*M_*N_)    // 131072 rows of the big GEMM
#define RB 128                // rows per row-block
#define NUM_RB (R_TOTAL/RB)   // 1024

// ---------------- scratch (device globals; no runtime alloc) ----------------
__device__ float g_he[B_*M_*D_];                           // 2 MB
__device__ float g_hd[B_*N_*D_];                           // 1 MB
__device__ __nv_bfloat16 g_w2b[C_*D_];                     // 1 MB
__device__ __nv_bfloat16 g_hid[(size_t)R_TOTAL * D_];      // 128 MB
__device__ __nv_bfloat16 g_logits[(size_t)R_TOTAL * C_];   // 268 MB

// ---------------- helpers ----------------
__device__ __forceinline__ uint32_t smem_u32(const void* p) {
    uint32_t a;
    asm("{ .reg .u64 t; cvta.to.shared.u64 t, %1; cvt.u32.u64 %0, t; }" : "=r"(a) : "l"(p));
    return a;
}
#define SW128(o) ((o) ^ (((o) >> 3) & 0x70))

__device__ __forceinline__ void cp16(uint32_t s, const void* g) {
    asm volatile("cp.async.cg.shared.global [%0], [%1], 16;" :: "r"(s), "l"(g));
}
#define CP_COMMIT() asm volatile("cp.async.commit_group;" ::: "memory")
#define CP_WAIT(n)  asm volatile("cp.async.wait_group %0;" :: "n"(n) : "memory")

__device__ __forceinline__ void ldsm_x4(uint32_t* r, uint32_t addr) {
    asm volatile("ldmatrix.sync.aligned.m8n8.x4.shared.b16 {%0,%1,%2,%3}, [%4];"
                 : "=r"(r[0]), "=r"(r[1]), "=r"(r[2]), "=r"(r[3]) : "r"(addr));
}
__device__ __forceinline__ void mma16816(float* c, const uint32_t* a, const uint32_t* b) {
    asm volatile(
        "mma.sync.aligned.m16n8k16.row.col.f32.bf16.bf16.f32 "
        "{%0,%1,%2,%3}, {%4,%5,%6,%7}, {%8,%9}, {%0,%1,%2,%3};"
        : "+f"(c[0]), "+f"(c[1]), "+f"(c[2]), "+f"(c[3])
        : "r"(a[0]), "r"(a[1]), "r"(a[2]), "r"(a[3]), "r"(b[0]), "r"(b[1]));
}

// ---------------- K0: w2 fp32 -> bf16 ----------------
__global__ void __launch_bounds__(256) k_w2conv(const float* __restrict__ w2) {
    int idx = (blockIdx.x * 256 + threadIdx.x) * 4;
    if (idx < C_ * D_) {
        float4 v = *(const float4*)(w2 + idx);
        __nv_bfloat16 o[4];
        o[0] = __float2bfloat16(v.x); o[1] = __float2bfloat16(v.y);
        o[2] = __float2bfloat16(v.z); o[3] = __float2bfloat16(v.w);
        *(uint2*)(g_w2b + idx) = *(uint2*)o;
    }
}

// ---------------- K1: he/hd = enc/dec @ w1 slices (tiled fp32 GEMM) ----------------
// CTA: 64 out-rows x 64 out-cols; 256 threads, 4x4 microtile; K chunks of 16.
__global__ void __launch_bounds__(256) k_fc1(const float* __restrict__ enc,
                                             const float* __restrict__ dec,
                                             const float* __restrict__ w1) {
    __shared__ float As[2][16][68];
    __shared__ float Ws[2][16][68];
    int tid = threadIdx.x;
    int rblk = blockIdx.x >> 3, cblk = blockIdx.x & 7;
    int row0 = rblk * 64, e0 = cblk * 64;

    const float* src; float* dst; int woff;
    if (row0 < B_ * M_) { src = enc + (size_t)row0 * D_; dst = g_he + (size_t)row0 * D_; woff = 0; }
    else {
        int r2 = row0 - B_ * M_;
        src = dec + (size_t)r2 * D_; dst = g_hd + (size_t)r2 * D_; woff = D_;
    }

    int lr = tid >> 2, lq = tid & 3;      // load: row 0..63, quad 0..3
    int ty = tid >> 4, tx = tid & 15;     // compute: 4-row group, 4-col group

    float4 ra, rw;
    auto fetch = [&](int kc) {
        ra = *(const float4*)(src + (size_t)lr * D_ + kc * 16 + lq * 4);
        rw = *(const float4*)(w1 + (size_t)(e0 + lr) * (2 * D_) + woff + kc * 16 + lq * 4);
    };
    auto stash = [&](int buf) {
        As[buf][lq * 4 + 0][lr] = ra.x; As[buf][lq * 4 + 1][lr] = ra.y;
        As[buf][lq * 4 + 2][lr] = ra.z; As[buf][lq * 4 + 3][lr] = ra.w;
        Ws[buf][lq * 4 + 0][lr] = rw.x; Ws[buf][lq * 4 + 1][lr] = rw.y;
        Ws[buf][lq * 4 + 2][lr] = rw.z; Ws[buf][lq * 4 + 3][lr] = rw.w;
    };

    float acc[4][4];
    #pragma unroll
    for (int i = 0; i < 4; i++)
        #pragma unroll
        for (int j = 0; j < 4; j++) acc[i][j] = 0.f;

    fetch(0);
    for (int kc = 0; kc < 32; kc++) {
        int buf = kc & 1;
        stash(buf);
        __syncthreads();
        if (kc < 31) fetch(kc + 1);
        #pragma unroll
        for (int k = 0; k < 16; k++) {
            float4 a = *(const float4*)&As[buf][k][ty * 4];
            float4 w = *(const float4*)&Ws[buf][k][tx * 4];
            float av[4] = {a.x, a.y, a.z, a.w};
            float wv[4] = {w.x, w.y, w.z, w.w};
            #pragma unroll
            for (int i = 0; i < 4; i++)
                #pragma unroll
                for (int j = 0; j < 4; j++) acc[i][j] += av[i] * wv[j];
        }
        __syncthreads();
    }
    #pragma unroll
    for (int i = 0; i < 4; i++) {
        float4 v; v.x = acc[i][0]; v.y = acc[i][1]; v.z = acc[i][2]; v.w = acc[i][3];
        *(float4*)(dst + (size_t)(ty * 4 + i) * D_ + e0 + tx * 4) = v;
    }
}

// ---------------- K2: hid = bf16(tanh(he + hd + b1)) ----------------
__global__ void __launch_bounds__(256) k_hid(const float* __restrict__ b1) {
    __shared__ float he_s[D_], b1_s[D_];
    int bm = blockIdx.x;             // b*256+m
    int b = bm >> 8;
    for (int i = threadIdx.x; i < D_; i += 256) {
        he_s[i] = g_he[(size_t)bm * D_ + i];
        b1_s[i] = b1[i];
    }
    __syncthreads();
    const float* hdb = g_hd + (size_t)b * N_ * D_;
    __nv_bfloat16* outp = g_hid + (size_t)bm * N_ * D_;
    for (int idx = threadIdx.x; idx < N_ * D_ / 8; idx += 256) {
        int n = idx >> 6, k = (idx & 63) * 8;
        float4 a0 = *(const float4*)(hdb + (size_t)n * D_ + k);
        float4 a1 = *(const float4*)(hdb + (size_t)n * D_ + k + 4);
        float v[8] = {a0.x, a0.y, a0.z, a0.w, a1.x, a1.y, a1.z, a1.w};
        __nv_bfloat16 o[8];
        #pragma unroll
        for (int j = 0; j < 8; j++) {
            float x = v[j] + he_s[k + j] + b1_s[k + j];
            float t; asm("tanh.approx.f32 %0, %1;" : "=f"(t) : "f"(x));
            o[j] = __float2bfloat16(t);
        }
        *(uint4*)(outp + (size_t)n * D_ + k) = *(uint4*)o;
    }
}

// ---------------- G1: fused GEMM (8 col-groups) + log-softmax + output ----------------
// smem layout (dynamic) — stage buffer now DEDICATED (no alias with A/B):
#define SA    0          // A tiles: 2 x 16384 (128 rows x 128B, SW128)
#define SB    32768      // B tiles: 2 x 16384
#define SB2   65536      // 1024 floats (full b2)
#define SPM   69632      // 128 x 2 floats
#define SPS   70656      // 128 x 2 floats
#define SPART 71680      // 128 rows x 8 cg x 2 floats = 8192 B
#define SLSE  79872      // 128 floats
#define STG   80384      // stage: 64 rows x 136 bf16 = 17408 B (dedicated)
#define SMEM_G1 97792
#define STG_STRIDE 272   // bytes per stage row (136 bf16)

__global__ void __launch_bounds__(256, 2)
k_gemm(float* __restrict__ out, const float* __restrict__ b2) {
    extern __shared__ char sm[];
    uint32_t sb = smem_u32(sm);
    int tid = threadIdx.x, wid = tid >> 5, lane = tid & 31;
    int rb = blockIdx.x;
    int m0 = (wid >> 1) * 32, n0 = (wid & 1) * 64;
    int g = lane >> 2, t4 = lane & 3;
    const float NEG_INF = __int_as_float(0xff800000);

    for (int i = tid; i < C_; i += 256) ((float*)(sm + SB2))[i] = b2[i];

    const __nv_bfloat16* Ag = g_hid + (size_t)rb * RB * D_;
    float* pmS = (float*)(sm + SPM);
    float* psS = (float*)(sm + SPS);
    float* part = (float*)(sm + SPART);
    __syncthreads();

    for (int cg = 0; cg < 8; cg++) {
        const __nv_bfloat16* Bg = g_w2b + (size_t)cg * 128 * D_;
        const float* b2s = (const float*)(sm + SB2) + cg * 128;

        float c[2][8][4];
        #pragma unroll
        for (int i = 0; i < 2; i++)
            #pragma unroll
            for (int j = 0; j < 8; j++)
                #pragma unroll
                for (int q = 0; q < 4; q++) c[i][j][q] = 0.f;

        auto load_tiles = [&](int kc, int buf) {
            uint32_t sa = sb + SA + buf * 16384;
            uint32_t sB = sb + SB + buf * 16384;
            #pragma unroll
            for (int i = 0; i < 4; i++) {
                int idx = tid + i * 256;          // 1024 chunks of 16B
                int row = idx >> 3, ck = idx & 7;
                const __nv_bfloat16* ga = Ag + (size_t)row * D_ + kc * 64 + ck * 8;
                const __nv_bfloat16* gb = Bg + (size_t)row * D_ + kc * 64 + ck * 8;
                uint32_t so = SW128(row * 128 + ck * 16);
                cp16(sa + so, ga);
                cp16(sB + so, gb);
            }
        };

        load_tiles(0, 0);
        CP_COMMIT();

        for (int kc = 0; kc < 8; kc++) {
            int buf = kc & 1;
            if (kc < 7) {
                load_tiles(kc + 1, buf ^ 1);
                CP_COMMIT();
                CP_WAIT(1);
            } else {
                CP_WAIT(0);
            }
            __syncthreads();
            uint32_t sa = sb + SA + buf * 16384;
            uint32_t sB = sb + SB + buf * 16384;
            #pragma unroll
            for (int ks = 0; ks < 4; ks++) {
                int k0 = ks * 16;
                uint32_t a[2][4];
                #pragma unroll
                for (int mt = 0; mt < 2; mt++) {
                    int row = m0 + mt * 16 + (lane & 15);
                    int cb = (k0 + ((lane >> 4) << 3)) * 2;
                    ldsm_x4(a[mt], sa + SW128(row * 128 + cb));
                }
                uint32_t b[8][2];
                #pragma unroll
                for (int ntp = 0; ntp < 4; ntp++) {
                    int row = n0 + ntp * 16 + ((lane & 16) >> 1) + (lane & 7);
                    int cb = (k0 + (lane & 8)) * 2;
                    uint32_t r[4];
                    ldsm_x4(r, sB + SW128(row * 128 + cb));
                    b[ntp * 2][0] = r[0]; b[ntp * 2][1] = r[1];
                    b[ntp * 2 + 1][0] = r[2]; b[ntp * 2 + 1][1] = r[3];
                }
                #pragma unroll
                for (int mt = 0; mt < 2; mt++)
                    #pragma unroll
                    for (int nt = 0; nt < 8; nt++)
                        mma16816(c[mt][nt], a[mt], b[nt]);
            }
            __syncthreads();
        }

        // ---- per-cg epilogue: b2 add + per-row (max,sum) from registers ----
        #pragma unroll
        for (int mt = 0; mt < 2; mt++) {
            #pragma unroll
            for (int half = 0; half < 2; half++) {
                int rl = m0 + mt * 16 + half * 8 + g;
                float mx = NEG_INF;
                #pragma unroll
                for (int nt = 0; nt < 8; nt++) {
                    int col = n0 + nt * 8 + t4 * 2;
                    float v0 = c[mt][nt][half * 2]     + b2s[col];
                    float v1 = c[mt][nt][half * 2 + 1] + b2s[col + 1];
                    c[mt][nt][half * 2] = v0;
                    c[mt][nt][half * 2 + 1] = v1;
                    mx = fmaxf(mx, fmaxf(v0, v1));
                }
                float sum = 0.f;
                #pragma unroll
                for (int nt = 0; nt < 8; nt++) {
                    sum += __expf(c[mt][nt][half * 2]     - mx);
                    sum += __expf(c[mt][nt][half * 2 + 1] - mx);
                }
                #pragma unroll
                for (int off = 1; off <= 2; off <<= 1) {
                    float om = __shfl_xor_sync(0xFFFFFFFFu, mx, off);
                    float os = __shfl_xor_sync(0xFFFFFFFFu, sum, off);
                    float nm = fmaxf(mx, om);
                    sum = sum * __expf(mx - nm) + os * __expf(om - nm);
                    mx = nm;
                }
                if (t4 == 0) {
                    pmS[rl * 2 + (wid & 1)] = mx;
                    psS[rl * 2 + (wid & 1)] = sum;
                }
            }
        }
        __syncthreads();

        if (tid < 128) {
            float ma = pmS[tid * 2], mb = pmS[tid * 2 + 1];
            float sa2 = psS[tid * 2], sbv = psS[tid * 2 + 1];
            float Mx = fmaxf(ma, mb);
            float S = sa2 * __expf(ma - Mx) + sbv * __expf(mb - Mx);
            part[tid * 16 + cg * 2]     = Mx;
            part[tid * 16 + cg * 2 + 1] = S;
        }

        // ---- stage bf16 logits in 2 batches of 64 rows (dedicated buffer) ----
        #pragma unroll
        for (int bat = 0; bat < 2; bat++) {
            if ((wid >> 2) == bat) {
                #pragma unroll
                for (int mt = 0; mt < 2; mt++)
                    #pragma unroll
                    for (int half = 0; half < 2; half++) {
                        int rl = m0 + mt * 16 + half * 8 + g - bat * 64;
                        #pragma unroll
                        for (int nt = 0; nt < 8; nt++) {
                            int col = n0 + nt * 8 + t4 * 2;
                            __nv_bfloat162 p;
                            p.x = __float2bfloat16(c[mt][nt][half * 2]);
                            p.y = __float2bfloat16(c[mt][nt][half * 2 + 1]);
                            *(uint32_t*)(sm + STG + rl * STG_STRIDE + col * 2) = *(uint32_t*)&p;
                        }
                    }
            }
            __syncthreads();
            #pragma unroll
            for (int i = 0; i < 4; i++) {       // 1024 chunks of 16B over 64x128
                int idx = tid + i * 256;
                int row = idx >> 4, ck = idx & 15;
                uint4 v = *(uint4*)(sm + STG + row * STG_STRIDE + ck * 16);
                *(uint4*)(g_logits + ((size_t)rb * RB + bat * 64 + row) * C_ + cg * 128 + ck * 8) = v;
            }
            __syncthreads();
        }
        // next cg's load_tiles touches only SA/SB — independent of STG stores
    }

    // ---- lse per row ----
    if (tid < 128) {
        float Mx = NEG_INF;
        #pragma unroll
        for (int i = 0; i < 8; i++) Mx = fmaxf(Mx, part[tid * 16 + i * 2]);
        float S = 0.f;
        #pragma unroll
        for (int i = 0; i < 8; i++)
            S += part[tid * 16 + i * 2 + 1] * __expf(part[tid * 16 + i * 2] - Mx);
        ((float*)(sm + SLSE))[tid] = Mx + __logf(S);
    }
    __syncthreads();

    // ---- pass 2: re-read own logits (hot in L2), subtract lse, write fp32 out ----
    const float* lseS = (const float*)(sm + SLSE);
    #pragma unroll
    for (int i = 0; i < 64; i++) {
        int idx = tid + i * 256;              // 16384 chunks of 16B over 128x1024
        int row = idx >> 7, ck = idx & 127;
        float lse = lseS[row];
        uint4 lv = *(const uint4*)(g_logits + ((size_t)rb * RB + row) * C_ + ck * 8);
        __nv_bfloat16* lb = (__nv_bfloat16*)&lv;
        float4 o0, o1;
        o0.x = __bfloat162float(lb[0]) - lse;
        o0.y = __bfloat162float(lb[1]) - lse;
        o0.z = __bfloat162float(lb[2]) - lse;
        o0.w = __bfloat162float(lb[3]) - lse;
        o1.x = __bfloat162float(lb[4]) - lse;
        o1.y = __bfloat162float(lb[5]) - lse;
        o1.z = __bfloat162float(lb[6]) - lse;
        o1.w = __bfloat162float(lb[7]) - lse;
        float* op = out + ((size_t)rb * RB + row) * C_ + ck * 8;
        *(float4*)op = o0;
        *(float4*)(op + 4) = o1;
    }
}

// ---------------- launch ----------------
extern "C" void kernel_launch(void* const* d_in, const int* in_sizes, int n_in,
                              void* d_out, int out_size) {
    const float* enc = (const float*)d_in[0];
    const float* dec = (const float*)d_in[1];
    const float* w1  = (const float*)d_in[2];
    const float* b1  = (const float*)d_in[3];
    const float* w2  = (const float*)d_in[4];
    const float* b2  = (const float*)d_in[5];
    float* out = (float*)d_out;

    k_w2conv<<<(C_ * D_ / 4 + 255) / 256, 256>>>(w2);
    k_fc1<<<(B_ * M_ + B_ * N_) / 64 * 8, 256>>>(enc, dec, w1);
    k_hid<<<B_ * M_, 256>>>(b1);
    static int smem_set = 0;
    if (!smem_set) {
        cudaFuncSetAttribute(k_gemm, cudaFuncAttributeMaxDynamicSharedMemorySize, SMEM_G1);
        smem_set = 1;
    }
    k_gemm<<<NUM_RB, 256, SMEM_G1>>>(out, b2);
}